// round 1
// baseline (speedup 1.0000x reference)
#include <cuda_runtime.h>
#include <math.h>

// KAN FFN: y2 = KAN2(KAN1(x))
// Each KAN layer:  y[n,o] = sum_i [ silu(x[n,i])*scale_base[i,o]
//                                 + sum_g B_g(x[n,i]) * coef[i,o,g]*scale_sp[i,o] ]
// Uniform grid => B-spline basis depends only on the scalar x; all knots and
// Cox-de Boor denominators are compile-time constants.
//
// Strategy: fused feature-expansion GEMM in fp32 using packed fma.rn.f32x2
// (2 rows per 64-bit register pair) -> 2x the FFMA pipe throughput.

#define D_MODEL 1024
#define KAN_HIDDEN 128
#define NBASIS 6          // NUM + K
#define NFEAT 7           // silu + 6 basis

// Inter-layer scratch (allocation-free rule: __device__ global)
__device__ float g_y1[16384 * KAN_HIDDEN];

// ---------------- packed f32x2 helpers ----------------
__device__ __forceinline__ unsigned long long pack2(float lo, float hi) {
    unsigned long long r;
    asm("mov.b64 %0, {%1, %2};" : "=l"(r) : "f"(lo), "f"(hi));
    return r;
}
__device__ __forceinline__ void unpack2(unsigned long long v, float& lo, float& hi) {
    asm("mov.b64 {%0, %1}, %2;" : "=f"(lo), "=f"(hi) : "l"(v));
}
__device__ __forceinline__ unsigned long long ffma2(unsigned long long a,
                                                    unsigned long long b,
                                                    unsigned long long c) {
    unsigned long long d;
    asm("fma.rn.f32x2 %0, %1, %2, %3;" : "=l"(d) : "l"(a), "l"(b), "l"(c));
    return d;
}

// ---------------- feature computation ----------------
// Knots: t[j] = (j-3)*(2/3) - 1, j = 0..9  (matches jnp.arange(-K,NUM+K+1)*h + lo in fp32)
__device__ __forceinline__ void kan_features(float x, float f[NFEAT]) {
    const float h = 2.0f / 3.0f;
    float t[10];
#pragma unroll
    for (int j = 0; j < 10; ++j) t[j] = (float)(j - 3) * h - 1.0f;

    float B[9];
#pragma unroll
    for (int j = 0; j < 9; ++j)
        B[j] = (x >= t[j] && x < t[j + 1]) ? 1.0f : 0.0f;

    // Cox-de Boor; denominators are constants -> reciprocals fold at compile time.
    // In-place ascending update is safe (new B[j] uses old B[j], old B[j+1]).
#pragma unroll
    for (int d = 1; d <= 3; ++d) {
#pragma unroll
        for (int j = 0; j < 9 - d; ++j) {
            float invL = 1.0f / (t[j + d] - t[j]);
            float invR = 1.0f / (t[j + d + 1] - t[j + 1]);
            B[j] = (x - t[j]) * invL * B[j] + (t[j + d + 1] - x) * invR * B[j + 1];
        }
    }

    float sg = 1.0f / (1.0f + expf(-x));
    f[0] = x * sg;            // silu
#pragma unroll
    for (int g = 0; g < NBASIS; ++g) f[1 + g] = B[g];
}

// ---------------- fused KAN layer kernel ----------------
// Block: 128 threads, one per output column of a 128-wide out tile.
// Row tile TR=32 rows; i processed in chunks of IC=16 through smem features.
template <int IN, int OUT>
__global__ void __launch_bounds__(128, 4)
kan_layer_kernel(const float* __restrict__ X,          // [N, IN]
                 const float* __restrict__ coef,       // [IN, OUT, 6]
                 const float* __restrict__ scale_base, // [IN, OUT]
                 const float* __restrict__ scale_sp,   // [IN, OUT]
                 float* __restrict__ Y,                // [N, OUT]
                 int N) {
    constexpr int TR = 32;
    constexpr int IC = 16;

    __shared__ __align__(16) float feat[IC][NFEAT][TR];   // 14 KB

    const int tid = threadIdx.x;
    const int rowBase = blockIdx.x * TR;
    const int o = blockIdx.y * 128 + tid;

    // featurize mapping: each thread loads one float4 of X (4 consecutive i)
    const int fr = tid >> 2;          // row within tile: 0..31
    const int fi = (tid & 3) * 4;     // i offset within chunk: 0,4,8,12

    unsigned long long acc2[TR / 2];  // packed accumulators: 2 rows each
#pragma unroll
    for (int k = 0; k < TR / 2; ++k) acc2[k] = 0ull;

    for (int i0 = 0; i0 < IN; i0 += IC) {
        __syncthreads();  // protect feat from previous iteration's readers

        // ---- featurize phase ----
        {
            const float4 xv = *reinterpret_cast<const float4*>(
                &X[(rowBase + fr) * IN + i0 + fi]);
            float f[NFEAT];
            kan_features(xv.x, f);
#pragma unroll
            for (int g = 0; g < NFEAT; ++g) feat[fi + 0][g][fr] = f[g];
            kan_features(xv.y, f);
#pragma unroll
            for (int g = 0; g < NFEAT; ++g) feat[fi + 1][g][fr] = f[g];
            kan_features(xv.z, f);
#pragma unroll
            for (int g = 0; g < NFEAT; ++g) feat[fi + 2][g][fr] = f[g];
            kan_features(xv.w, f);
#pragma unroll
            for (int g = 0; g < NFEAT; ++g) feat[fi + 3][g][fr] = f[g];
        }
        __syncthreads();

        // ---- compute phase ----
#pragma unroll 1
        for (int ii = 0; ii < IC; ++ii) {
            const int wi = (i0 + ii) * OUT + o;
            const float* cp = coef + (size_t)wi * 6;       // 24B-aligned -> float2 ok
            const float2 c01 = *reinterpret_cast<const float2*>(cp);
            const float2 c23 = *reinterpret_cast<const float2*>(cp + 2);
            const float2 c45 = *reinterpret_cast<const float2*>(cp + 4);
            const float ssp = scale_sp[wi];
            const float sb  = scale_base[wi];

            unsigned long long w[NFEAT];
            {
                float w1 = c01.x * ssp, w2 = c01.y * ssp;
                float w3 = c23.x * ssp, w4 = c23.y * ssp;
                float w5 = c45.x * ssp, w6 = c45.y * ssp;
                w[0] = pack2(sb, sb);
                w[1] = pack2(w1, w1);
                w[2] = pack2(w2, w2);
                w[3] = pack2(w3, w3);
                w[4] = pack2(w4, w4);
                w[5] = pack2(w5, w5);
                w[6] = pack2(w6, w6);
            }

            // feat[ii] viewed as ulonglong2 rows: g-row stride = 32 floats = 8 ull2
            const ulonglong2* fp =
                reinterpret_cast<const ulonglong2*>(&feat[ii][0][0]);
#pragma unroll
            for (int r4 = 0; r4 < TR / 4; ++r4) {
#pragma unroll
                for (int g = 0; g < NFEAT; ++g) {
                    const ulonglong2 fv = fp[g * 8 + r4];  // broadcast LDS.128
                    acc2[2 * r4 + 0] = ffma2(fv.x, w[g], acc2[2 * r4 + 0]);
                    acc2[2 * r4 + 1] = ffma2(fv.y, w[g], acc2[2 * r4 + 1]);
                }
            }
        }
    }

    // ---- epilogue: unpack and store (lanes -> consecutive o, coalesced) ----
#pragma unroll
    for (int r4 = 0; r4 < TR / 4; ++r4) {
        float a, b, c, d;
        unpack2(acc2[2 * r4 + 0], a, b);
        unpack2(acc2[2 * r4 + 1], c, d);
        const int row = rowBase + 4 * r4;
        Y[(size_t)(row + 0) * OUT + o] = a;
        Y[(size_t)(row + 1) * OUT + o] = b;
        Y[(size_t)(row + 2) * OUT + o] = c;
        Y[(size_t)(row + 3) * OUT + o] = d;
    }
}

// ---------------- launcher ----------------
extern "C" void kernel_launch(void* const* d_in, const int* in_sizes, int n_in,
                              void* d_out, int out_size) {
    const float* x     = (const float*)d_in[0];
    const float* coef1 = (const float*)d_in[1];
    const float* sb1   = (const float*)d_in[2];
    const float* ssp1  = (const float*)d_in[3];
    const float* coef2 = (const float*)d_in[4];
    const float* sb2   = (const float*)d_in[5];
    const float* ssp2  = (const float*)d_in[6];
    float* out = (float*)d_out;

    const int N = in_sizes[0] / D_MODEL;   // 16384

    float* y1 = nullptr;
    cudaGetSymbolAddress((void**)&y1, g_y1);

    // Layer 1: 1024 -> 128
    kan_layer_kernel<D_MODEL, KAN_HIDDEN>
        <<<dim3(N / 32, KAN_HIDDEN / 128), 128>>>(x, coef1, sb1, ssp1, y1, N);
    // Layer 2: 128 -> 1024
    kan_layer_kernel<KAN_HIDDEN, D_MODEL>
        <<<dim3(N / 32, D_MODEL / 128), 128>>>(y1, coef2, sb2, ssp2, out, N);
}